// round 3
// baseline (speedup 1.0000x reference)
#include <cuda_runtime.h>

#define N_NODES 65536
#define N_EDGES 1048576
#define IN_F 128
#define HID 64

// ---------------- scratch (device globals; no allocation allowed) ----------
__device__ float    g_h0[N_NODES * HID];   // 16 MB
__device__ float    g_h1[N_NODES * HID];   // 16 MB
__device__ float    g_rn[N_NODES];         // 1/max(||h||, eps)
__device__ unsigned g_m[N_NODES];          // encoded segment max
__device__ float    g_s[N_NODES];          // softmax denominator
__device__ float    g_e[N_EDGES];          // per-edge logit, then exp

// order-preserving float<->uint map (works for -inf too)
__device__ __forceinline__ unsigned encf(float f) {
    unsigned u = __float_as_uint(f);
    return (u & 0x80000000u) ? ~u : (u | 0x80000000u);
}
__device__ __forceinline__ float decf(unsigned u) {
    return (u & 0x80000000u) ? __uint_as_float(u & 0x7fffffffu)
                             : __uint_as_float(~u);
}

// ---------------- proj: h = relu(features @ W1 + b1) -----------------------
__global__ __launch_bounds__(256) void proj_kernel(
    const float* __restrict__ feat, const float* __restrict__ W1,
    const float* __restrict__ b1, float* __restrict__ out)
{
    __shared__ float sW[IN_F * HID];   // 32 KB
    __shared__ float sF[4][IN_F];      // 2 KB
    int tid = threadIdx.x;
    for (int i = tid; i < IN_F * HID; i += 256) sW[i] = W1[i];
    int row0 = blockIdx.x * 4;
    for (int i = tid; i < 4 * IN_F; i += 256)
        sF[i >> 7][i & 127] = feat[row0 * IN_F + i];
    __syncthreads();
    int r = tid >> 6, j = tid & 63;
    float acc = b1[j];
#pragma unroll
    for (int k = 0; k < IN_F; k++)
        acc = fmaf(sF[r][k], sW[k * HID + j], acc);
    out[(row0 + r) * HID + j] = fmaxf(acc, 0.0f);
}

// ---------------- per-node reciprocal L2 norm ------------------------------
__global__ __launch_bounds__(256) void rnorm_kernel(
    const float* __restrict__ h, float* __restrict__ rn)
{
    int warp = (blockIdx.x * blockDim.x + threadIdx.x) >> 5;
    int lane = threadIdx.x & 31;
    if (warp >= N_NODES) return;
    float2 v = *(const float2*)(h + warp * HID + lane * 2);
    float ss = v.x * v.x + v.y * v.y;
#pragma unroll
    for (int o = 16; o; o >>= 1) ss += __shfl_xor_sync(0xffffffffu, ss, o);
    if (lane == 0) rn[warp] = 1.0f / fmaxf(sqrtf(ss), 1e-12f);
}

// ---------------- init: zero accumulator, reset m/s ------------------------
__global__ __launch_bounds__(256) void init_kernel(
    float* __restrict__ hnext, unsigned* __restrict__ m, float* __restrict__ s)
{
    int i = blockIdx.x * blockDim.x + threadIdx.x;
    ((float4*)hnext)[i] = make_float4(0.f, 0.f, 0.f, 0.f);   // N*HID/4 threads
    if (i < N_NODES) { m[i] = 0x007FFFFFu /* enc(-inf) */; s[i] = 0.0f; }
}

// ---------------- edge pass 1: logits + segment max ------------------------
__global__ __launch_bounds__(256) void edge1_kernel(
    const int* __restrict__ src, const int* __restrict__ dst,
    const float* __restrict__ h, const float* __restrict__ rn,
    const float* __restrict__ betas, int layer,
    float* __restrict__ e, unsigned* __restrict__ m)
{
    int eid  = (blockIdx.x * blockDim.x + threadIdx.x) >> 5;
    int lane = threadIdx.x & 31;
    if (eid >= N_EDGES) return;
    int sn = __ldg(src + eid);
    int dn = __ldg(dst + eid);
    float2 a = *(const float2*)(h + sn * HID + lane * 2);
    float2 b = *(const float2*)(h + dn * HID + lane * 2);
    float dot = a.x * b.x + a.y * b.y;
#pragma unroll
    for (int o = 16; o; o >>= 1) dot += __shfl_xor_sync(0xffffffffu, dot, o);
    if (lane == 0) {
        float ev = __ldg(betas + layer) * dot * rn[sn] * rn[dn];
        e[eid] = ev;
        atomicMax(m + dn, encf(ev));
    }
}

// ---------------- edge pass 2: exp + segment sum ---------------------------
__global__ __launch_bounds__(256) void edge2_kernel(
    const int* __restrict__ dst, float* __restrict__ e,
    float* __restrict__ s, const unsigned* __restrict__ m)
{
    int eid = blockIdx.x * blockDim.x + threadIdx.x;
    if (eid >= N_EDGES) return;
    int dn = __ldg(dst + eid);
    float ex = expf(e[eid] - decf(m[dn]));
    e[eid] = ex;
    atomicAdd(s + dn, ex);
}

// ---------------- edge pass 3: weighted aggregation ------------------------
__global__ __launch_bounds__(256) void edge3_kernel(
    const int* __restrict__ src, const int* __restrict__ dst,
    const float* __restrict__ ex, const float* __restrict__ s,
    const float* __restrict__ h, float* __restrict__ out)
{
    int eid  = (blockIdx.x * blockDim.x + threadIdx.x) >> 5;
    int lane = threadIdx.x & 31;
    if (eid >= N_EDGES) return;
    int sn = __ldg(src + eid);
    int dn = __ldg(dst + eid);
    float w = ex[eid] / s[dn];
    float2 a = *(const float2*)(h + sn * HID + lane * 2);
    float* p = out + dn * HID + lane * 2;
    asm volatile("red.global.add.v2.f32 [%0], {%1, %2};"
                 :: "l"(p), "f"(w * a.x), "f"(w * a.y) : "memory");
}

// ---------------- cls: out = h @ W2 + b2 -----------------------------------
__global__ __launch_bounds__(256) void cls_kernel(
    const float* __restrict__ h, const float* __restrict__ W2,
    const float* __restrict__ b2, float* __restrict__ out)
{
    __shared__ float sW[HID * HID];   // 16 KB
    __shared__ float sF[4][HID];
    int tid = threadIdx.x;
    for (int i = tid; i < HID * HID; i += 256) sW[i] = W2[i];
    int row0 = blockIdx.x * 4;
    for (int i = tid; i < 4 * HID; i += 256)
        sF[i >> 6][i & 63] = h[row0 * HID + i];
    __syncthreads();
    int r = tid >> 6, j = tid & 63;
    float acc = b2[j];
#pragma unroll
    for (int k = 0; k < HID; k++)
        acc = fmaf(sF[r][k], sW[k * HID + j], acc);
    out[(row0 + r) * HID + j] = acc;
}

// ---------------------------------------------------------------------------
extern "C" void kernel_launch(void* const* d_in, const int* in_sizes, int n_in,
                              void* d_out, int out_size)
{
    const float* feat  = (const float*)d_in[0];
    const int*   src   = (const int*)  d_in[1];
    const int*   dst   = (const int*)  d_in[2];
    const float* W1    = (const float*)d_in[3];
    const float* b1    = (const float*)d_in[4];
    const float* W2    = (const float*)d_in[5];
    const float* b2    = (const float*)d_in[6];
    const float* betas = (const float*)d_in[7];

    float *h0, *h1, *rn, *s, *e; unsigned* m;
    cudaGetSymbolAddress((void**)&h0, g_h0);
    cudaGetSymbolAddress((void**)&h1, g_h1);
    cudaGetSymbolAddress((void**)&rn, g_rn);
    cudaGetSymbolAddress((void**)&m,  g_m);
    cudaGetSymbolAddress((void**)&s,  g_s);
    cudaGetSymbolAddress((void**)&e,  g_e);

    proj_kernel<<<N_NODES / 4, 256>>>(feat, W1, b1, h0);

    float* hin = h0;
    float* hout = h1;
    for (int layer = 0; layer < 2; layer++) {
        rnorm_kernel<<<N_NODES * 32 / 256, 256>>>(hin, rn);
        init_kernel<<<(N_NODES * HID / 4) / 256, 256>>>(hout, m, s);
        edge1_kernel<<<N_EDGES * 32 / 256, 256>>>(src, dst, hin, rn, betas, layer, e, m);
        edge2_kernel<<<N_EDGES / 256, 256>>>(dst, e, s, m);
        edge3_kernel<<<N_EDGES * 32 / 256, 256>>>(src, dst, e, s, hin, hout);
        float* t = hin; hin = hout; hout = t;
    }

    cls_kernel<<<N_NODES / 4, 256>>>(hin, W2, b2, (float*)d_out);
}

// round 4
// speedup vs baseline: 3.4972x; 3.4972x over previous
#include <cuda_runtime.h>
#include <math_constants.h>

#define N_NODES 65536
#define N_EDGES 1048576
#define IN_F 128
#define HID 64

// ---------------- scratch (device globals; no allocation allowed) ----------
__device__ float g_h0[N_NODES * HID];   // 16 MB
__device__ float g_h1[N_NODES * HID];   // 16 MB
__device__ float g_rn[N_NODES];         // 1/max(||h||, eps)
__device__ int   g_deg[N_NODES];
__device__ int   g_off[N_NODES + 1];
__device__ int   g_cur[N_NODES];
__device__ int   g_bsum[256];
__device__ int   g_csr[N_EDGES];        // src node id, grouped by dst

// ---------------- CSR build --------------------------------------------------
__global__ __launch_bounds__(256) void zero_deg_kernel(int* __restrict__ deg) {
    deg[blockIdx.x * 256 + threadIdx.x] = 0;
}

__global__ __launch_bounds__(256) void hist_kernel(
    const int* __restrict__ dst, int* __restrict__ deg) {
    int i = blockIdx.x * 256 + threadIdx.x;
    atomicAdd(deg + __ldg(dst + i), 1);
}

// per-block inclusive scan of 256 degs -> exclusive offsets + block sum
__global__ __launch_bounds__(256) void scan1_kernel(
    const int* __restrict__ deg, int* __restrict__ off, int* __restrict__ bsum) {
    __shared__ int s[256];
    int t = threadIdx.x;
    int g = blockIdx.x * 256 + t;
    int d = deg[g];
    s[t] = d;
    __syncthreads();
#pragma unroll
    for (int o = 1; o < 256; o <<= 1) {
        int v = (t >= o) ? s[t - o] : 0;
        __syncthreads();
        s[t] += v;
        __syncthreads();
    }
    off[g] = s[t] - d;                 // exclusive within block
    if (t == 255) bsum[blockIdx.x] = s[255];
}

__global__ __launch_bounds__(256) void scan2_kernel(int* __restrict__ bsum) {
    __shared__ int s[256];
    int t = threadIdx.x;
    int d = bsum[t];
    s[t] = d;
    __syncthreads();
#pragma unroll
    for (int o = 1; o < 256; o <<= 1) {
        int v = (t >= o) ? s[t - o] : 0;
        __syncthreads();
        s[t] += v;
        __syncthreads();
    }
    bsum[t] = s[t] - d;                // exclusive block offsets
}

__global__ __launch_bounds__(256) void scan3_kernel(
    int* __restrict__ off, const int* __restrict__ bsum, int* __restrict__ cur) {
    int i = blockIdx.x * 256 + threadIdx.x;
    int v = off[i] + bsum[i >> 8];
    off[i] = v;
    cur[i] = v;
    if (i == 0) off[N_NODES] = N_EDGES;
}

__global__ __launch_bounds__(256) void scatter_kernel(
    const int* __restrict__ src, const int* __restrict__ dst,
    int* __restrict__ cur, int* __restrict__ csr) {
    int i = blockIdx.x * 256 + threadIdx.x;
    int p = atomicAdd(cur + __ldg(dst + i), 1);
    csr[p] = __ldg(src + i);
}

// ---------------- proj: h = relu(features @ W1 + b1), 16 rows/block ---------
__global__ __launch_bounds__(256) void proj_kernel(
    const float* __restrict__ feat, const float* __restrict__ W1,
    const float* __restrict__ b1, float* __restrict__ out)
{
    __shared__ float sW[IN_F * HID];   // 32 KB
    __shared__ float sF[16][IN_F];     // 8 KB
    int tid = threadIdx.x;
    for (int i = tid; i < IN_F * HID; i += 256) sW[i] = W1[i];
    int row0 = blockIdx.x * 16;
    for (int i = tid; i < 16 * IN_F; i += 256)
        sF[i >> 7][i & 127] = feat[row0 * IN_F + i];
    __syncthreads();
    int rg = tid >> 6, j = tid & 63;
    float acc0 = b1[j], acc1 = acc0, acc2 = acc0, acc3 = acc0;
#pragma unroll
    for (int k = 0; k < IN_F; k++) {
        float w = sW[k * HID + j];
        acc0 = fmaf(sF[rg     ][k], w, acc0);
        acc1 = fmaf(sF[rg +  4][k], w, acc1);
        acc2 = fmaf(sF[rg +  8][k], w, acc2);
        acc3 = fmaf(sF[rg + 12][k], w, acc3);
    }
    out[(row0 + rg     ) * HID + j] = fmaxf(acc0, 0.0f);
    out[(row0 + rg +  4) * HID + j] = fmaxf(acc1, 0.0f);
    out[(row0 + rg +  8) * HID + j] = fmaxf(acc2, 0.0f);
    out[(row0 + rg + 12) * HID + j] = fmaxf(acc3, 0.0f);
}

// ---------------- per-node reciprocal L2 norm -------------------------------
__global__ __launch_bounds__(256) void rnorm_kernel(
    const float* __restrict__ h, float* __restrict__ rn)
{
    int warp = (blockIdx.x * blockDim.x + threadIdx.x) >> 5;
    int lane = threadIdx.x & 31;
    float2 v = *(const float2*)(h + warp * HID + lane * 2);
    float ss = v.x * v.x + v.y * v.y;
#pragma unroll
    for (int o = 16; o; o >>= 1) ss += __shfl_xor_sync(0xffffffffu, ss, o);
    if (lane == 0) rn[warp] = 1.0f / fmaxf(sqrtf(ss), 1e-12f);
}

// ---------------- fused AGNN layer: warp per dst node, online softmax -------
__global__ __launch_bounds__(256) void layer_kernel(
    const int* __restrict__ csr, const int* __restrict__ off,
    const float* __restrict__ h, const float* __restrict__ rn,
    const float* __restrict__ betas, int layer,
    float* __restrict__ out)
{
    int node = (blockIdx.x * blockDim.x + threadIdx.x) >> 5;
    int lane = threadIdx.x & 31;
    const unsigned FULL = 0xffffffffu;

    int s0 = off[node], s1 = off[node + 1];
    float beta = __ldg(betas + layer);
    float2 d = *(const float2*)(h + node * HID + lane * 2);
    float rd = rn[node];

    float m = -CUDART_INF_F;
    float ss = 0.0f, ax = 0.0f, ay = 0.0f;

    for (int base = s0; base < s1; base += 32) {
        int cnt = min(32, s1 - base);
        int inb = (base + lane < s1);
        int idx = inb ? __ldg(csr + base + lane) : 0;
        float rnl = inb ? rn[idx] : 0.0f;
        for (int j = 0; j < cnt; j++) {
            int   sn  = __shfl_sync(FULL, idx, j);
            float rns = __shfl_sync(FULL, rnl, j);
            float2 a = *(const float2*)(h + sn * HID + lane * 2);
            float dot = d.x * a.x + d.y * a.y;
#pragma unroll
            for (int o = 16; o; o >>= 1)
                dot += __shfl_xor_sync(FULL, dot, o);
            float e  = beta * dot * rd * rns;
            float mn = fmaxf(m, e);
            float sc = __expf(m - mn);
            float w  = __expf(e - mn);
            ss = ss * sc + w;
            ax = ax * sc + w * a.x;
            ay = ay * sc + w * a.y;
            m = mn;
        }
    }
    float inv = (s1 > s0) ? __frcp_rn(ss) : 0.0f;
    float2 o2; o2.x = ax * inv; o2.y = ay * inv;
    *(float2*)(out + node * HID + lane * 2) = o2;
}

// ---------------- cls: out = h @ W2 + b2, 16 rows/block ---------------------
__global__ __launch_bounds__(256) void cls_kernel(
    const float* __restrict__ h, const float* __restrict__ W2,
    const float* __restrict__ b2, float* __restrict__ out)
{
    __shared__ float sW[HID * HID];    // 16 KB
    __shared__ float sF[16][HID];      // 4 KB
    int tid = threadIdx.x;
    for (int i = tid; i < HID * HID; i += 256) sW[i] = W2[i];
    int row0 = blockIdx.x * 16;
    for (int i = tid; i < 16 * HID; i += 256)
        sF[i >> 6][i & 63] = h[row0 * HID + i];
    __syncthreads();
    int rg = tid >> 6, j = tid & 63;
    float acc0 = b2[j], acc1 = acc0, acc2 = acc0, acc3 = acc0;
#pragma unroll
    for (int k = 0; k < HID; k++) {
        float w = sW[k * HID + j];
        acc0 = fmaf(sF[rg     ][k], w, acc0);
        acc1 = fmaf(sF[rg +  4][k], w, acc1);
        acc2 = fmaf(sF[rg +  8][k], w, acc2);
        acc3 = fmaf(sF[rg + 12][k], w, acc3);
    }
    out[(row0 + rg     ) * HID + j] = acc0;
    out[(row0 + rg +  4) * HID + j] = acc1;
    out[(row0 + rg +  8) * HID + j] = acc2;
    out[(row0 + rg + 12) * HID + j] = acc3;
}

// ---------------------------------------------------------------------------
extern "C" void kernel_launch(void* const* d_in, const int* in_sizes, int n_in,
                              void* d_out, int out_size)
{
    const float* feat  = (const float*)d_in[0];
    const int*   src   = (const int*)  d_in[1];
    const int*   dst   = (const int*)  d_in[2];
    const float* W1    = (const float*)d_in[3];
    const float* b1    = (const float*)d_in[4];
    const float* W2    = (const float*)d_in[5];
    const float* b2    = (const float*)d_in[6];
    const float* betas = (const float*)d_in[7];

    float *h0, *h1, *rn; int *deg, *off, *cur, *bsum, *csr;
    cudaGetSymbolAddress((void**)&h0,   g_h0);
    cudaGetSymbolAddress((void**)&h1,   g_h1);
    cudaGetSymbolAddress((void**)&rn,   g_rn);
    cudaGetSymbolAddress((void**)&deg,  g_deg);
    cudaGetSymbolAddress((void**)&off,  g_off);
    cudaGetSymbolAddress((void**)&cur,  g_cur);
    cudaGetSymbolAddress((void**)&bsum, g_bsum);
    cudaGetSymbolAddress((void**)&csr,  g_csr);

    // CSR by destination (built once per launch, reused by both layers)
    zero_deg_kernel<<<N_NODES / 256, 256>>>(deg);
    hist_kernel<<<N_EDGES / 256, 256>>>(dst, deg);
    scan1_kernel<<<N_NODES / 256, 256>>>(deg, off, bsum);
    scan2_kernel<<<1, 256>>>(bsum);
    scan3_kernel<<<N_NODES / 256, 256>>>(off, bsum, cur);
    scatter_kernel<<<N_EDGES / 256, 256>>>(src, dst, cur, csr);

    proj_kernel<<<N_NODES / 16, 256>>>(feat, W1, b1, h0);

    float* hin = h0;
    float* hout = h1;
    for (int layer = 0; layer < 2; layer++) {
        rnorm_kernel<<<N_NODES * 32 / 256, 256>>>(hin, rn);
        layer_kernel<<<N_NODES * 32 / 256, 256>>>(csr, off, hin, rn, betas, layer, hout);
        float* t = hin; hin = hout; hout = t;
    }

    cls_kernel<<<N_NODES / 16, 256>>>(hin, W2, b2, (float*)d_out);
}

// round 5
// speedup vs baseline: 4.2166x; 1.2057x over previous
#include <cuda_runtime.h>
#include <math_constants.h>

#define N_NODES 65536
#define N_EDGES 1048576
#define IN_F 128
#define HID 64

// ---------------- scratch (device globals; no allocation allowed) ----------
__device__ float g_h0[N_NODES * HID];   // 16 MB
__device__ float g_h1[N_NODES * HID];   // 16 MB
__device__ float g_rnA[N_NODES];        // 1/max(||h||, eps) ping
__device__ float g_rnB[N_NODES];        // pong
__device__ int   g_deg[N_NODES];
__device__ int   g_off[N_NODES + 1];
__device__ int   g_cur[N_NODES];
__device__ int   g_bsum[256];
__device__ int   g_csr[N_EDGES];        // src node id, grouped by dst

// ---------------- CSR build --------------------------------------------------
__global__ __launch_bounds__(256) void zero_deg_kernel(int* __restrict__ deg) {
    deg[blockIdx.x * 256 + threadIdx.x] = 0;
}

__global__ __launch_bounds__(256) void hist_kernel(
    const int* __restrict__ dst, int* __restrict__ deg) {
    int i = blockIdx.x * 256 + threadIdx.x;
    atomicAdd(deg + __ldg(dst + i), 1);
}

// per-block inclusive scan of 256 degs -> exclusive offsets + block sum
__global__ __launch_bounds__(256) void scan1_kernel(
    const int* __restrict__ deg, int* __restrict__ off, int* __restrict__ bsum) {
    __shared__ int s[256];
    int t = threadIdx.x;
    int g = blockIdx.x * 256 + t;
    int d = deg[g];
    s[t] = d;
    __syncthreads();
#pragma unroll
    for (int o = 1; o < 256; o <<= 1) {
        int v = (t >= o) ? s[t - o] : 0;
        __syncthreads();
        s[t] += v;
        __syncthreads();
    }
    off[g] = s[t] - d;                 // exclusive within block
    if (t == 255) bsum[blockIdx.x] = s[255];
}

// fused: every block scans the 256 block sums redundantly in smem,
// then applies global offsets (removes the grid=1 serializer kernel)
__global__ __launch_bounds__(256) void scan23_kernel(
    int* __restrict__ off, const int* __restrict__ bsum, int* __restrict__ cur) {
    __shared__ int s[256];
    int t = threadIdx.x;
    int d = bsum[t];
    s[t] = d;
    __syncthreads();
#pragma unroll
    for (int o = 1; o < 256; o <<= 1) {
        int v = (t >= o) ? s[t - o] : 0;
        __syncthreads();
        s[t] += v;
        __syncthreads();
    }
    // s[b] is inclusive; exclusive offset of block b = s[b] - bsum[b]
    __syncthreads();
    int i = blockIdx.x * 256 + t;
    int b = i >> 8;
    int excl = s[b] - bsum[b];
    int v = off[i] + excl;
    off[i] = v;
    cur[i] = v;
    if (i == 0) off[N_NODES] = N_EDGES;
}

__global__ __launch_bounds__(256) void scatter_kernel(
    const int* __restrict__ src, const int* __restrict__ dst,
    int* __restrict__ cur, int* __restrict__ csr) {
    int i = blockIdx.x * 256 + threadIdx.x;
    int p = atomicAdd(cur + __ldg(dst + i), 1);
    csr[p] = __ldg(src + i);
}

// ---------------- proj: h = relu(features @ W1 + b1) + fused row norms ------
__global__ __launch_bounds__(256) void proj_kernel(
    const float* __restrict__ feat, const float* __restrict__ W1,
    const float* __restrict__ b1, float* __restrict__ out,
    float* __restrict__ rn)
{
    __shared__ float sW[IN_F * HID];   // 32 KB
    __shared__ float sF[16][IN_F];     // 8 KB
    __shared__ float sN[16];
    int tid = threadIdx.x;
    if (tid < 16) sN[tid] = 0.0f;
    for (int i = tid; i < IN_F * HID; i += 256) sW[i] = W1[i];
    int row0 = blockIdx.x * 16;
    for (int i = tid; i < 16 * IN_F; i += 256)
        sF[i >> 7][i & 127] = feat[row0 * IN_F + i];
    __syncthreads();
    int rg = tid >> 6, j = tid & 63;
    float acc0 = b1[j], acc1 = acc0, acc2 = acc0, acc3 = acc0;
#pragma unroll
    for (int k = 0; k < IN_F; k++) {
        float w = sW[k * HID + j];
        acc0 = fmaf(sF[rg     ][k], w, acc0);
        acc1 = fmaf(sF[rg +  4][k], w, acc1);
        acc2 = fmaf(sF[rg +  8][k], w, acc2);
        acc3 = fmaf(sF[rg + 12][k], w, acc3);
    }
    acc0 = fmaxf(acc0, 0.0f); acc1 = fmaxf(acc1, 0.0f);
    acc2 = fmaxf(acc2, 0.0f); acc3 = fmaxf(acc3, 0.0f);
    out[(row0 + rg     ) * HID + j] = acc0;
    out[(row0 + rg +  4) * HID + j] = acc1;
    out[(row0 + rg +  8) * HID + j] = acc2;
    out[(row0 + rg + 12) * HID + j] = acc3;
    // fused row-norm: reduce acc^2 across the 64 threads (2 warps) of each row
    float p0 = acc0 * acc0, p1 = acc1 * acc1;
    float p2 = acc2 * acc2, p3 = acc3 * acc3;
#pragma unroll
    for (int o = 16; o; o >>= 1) {
        p0 += __shfl_xor_sync(0xffffffffu, p0, o);
        p1 += __shfl_xor_sync(0xffffffffu, p1, o);
        p2 += __shfl_xor_sync(0xffffffffu, p2, o);
        p3 += __shfl_xor_sync(0xffffffffu, p3, o);
    }
    if ((tid & 31) == 0) {
        atomicAdd(&sN[rg     ], p0);
        atomicAdd(&sN[rg +  4], p1);
        atomicAdd(&sN[rg +  8], p2);
        atomicAdd(&sN[rg + 12], p3);
    }
    __syncthreads();
    if (tid < 16)
        rn[row0 + tid] = 1.0f / fmaxf(sqrtf(sN[tid]), 1e-12f);
}

// ---------------- fused AGNN layer: warp/dst, constant-shift softmax --------
__global__ __launch_bounds__(256) void layer_kernel(
    const int* __restrict__ csr, const int* __restrict__ off,
    const float* __restrict__ h, const float* __restrict__ rn_in,
    const float* __restrict__ betas, int layer,
    float* __restrict__ out, float* __restrict__ rn_out)
{
    int node = (blockIdx.x * blockDim.x + threadIdx.x) >> 5;
    int lane = threadIdx.x & 31;
    const unsigned FULL = 0xffffffffu;

    int s0 = off[node], s1 = off[node + 1];
    float beta = __ldg(betas + layer);
    float B = fabsf(beta);                       // analytic max of beta*cos
    float2 d = *(const float2*)(h + node * HID + lane * 2);
    float qs = beta * rn_in[node];
    float qx = d.x * qs, qy = d.y * qs;          // folded per-lane query

    float ss = 0.0f, ax = 0.0f, ay = 0.0f;

    for (int base = s0; base < s1; base += 32) {
        int cnt = min(32, s1 - base);
        int inb = (base + lane < s1);
        int idx = inb ? __ldg(csr + base + lane) : 0;
        float rnl = inb ? rn_in[idx] : 0.0f;
        int j = 0;
        for (; j + 1 < cnt; j += 2) {
            int   sn0 = __shfl_sync(FULL, idx, j);
            int   sn1 = __shfl_sync(FULL, idx, j + 1);
            float rs0 = __shfl_sync(FULL, rnl, j);
            float rs1 = __shfl_sync(FULL, rnl, j + 1);
            float2 a0 = *(const float2*)(h + sn0 * HID + lane * 2);
            float2 a1 = *(const float2*)(h + sn1 * HID + lane * 2);
            float d0 = qx * a0.x + qy * a0.y;
            float d1 = qx * a1.x + qy * a1.y;
#pragma unroll
            for (int o = 16; o; o >>= 1) {
                d0 += __shfl_xor_sync(FULL, d0, o);
                d1 += __shfl_xor_sync(FULL, d1, o);
            }
            float w0 = __expf(fmaf(d0, rs0, -B));
            float w1 = __expf(fmaf(d1, rs1, -B));
            ss += w0 + w1;
            ax = fmaf(w0, a0.x, ax); ax = fmaf(w1, a1.x, ax);
            ay = fmaf(w0, a0.y, ay); ay = fmaf(w1, a1.y, ay);
        }
        if (j < cnt) {
            int   sn0 = __shfl_sync(FULL, idx, j);
            float rs0 = __shfl_sync(FULL, rnl, j);
            float2 a0 = *(const float2*)(h + sn0 * HID + lane * 2);
            float d0 = qx * a0.x + qy * a0.y;
#pragma unroll
            for (int o = 16; o; o >>= 1)
                d0 += __shfl_xor_sync(FULL, d0, o);
            float w0 = __expf(fmaf(d0, rs0, -B));
            ss += w0;
            ax = fmaf(w0, a0.x, ax);
            ay = fmaf(w0, a0.y, ay);
        }
    }
    float inv = (s1 > s0) ? __frcp_rn(ss) : 0.0f;
    float2 o2; o2.x = ax * inv; o2.y = ay * inv;
    *(float2*)(out + node * HID + lane * 2) = o2;

    // fused rn of the output vector (for the next layer)
    float ns = o2.x * o2.x + o2.y * o2.y;
#pragma unroll
    for (int o = 16; o; o >>= 1) ns += __shfl_xor_sync(FULL, ns, o);
    if (lane == 0)
        rn_out[node] = 1.0f / fmaxf(sqrtf(ns), 1e-12f);
}

// ---------------- cls: out = h @ W2 + b2, 16 rows/block ---------------------
__global__ __launch_bounds__(256) void cls_kernel(
    const float* __restrict__ h, const float* __restrict__ W2,
    const float* __restrict__ b2, float* __restrict__ out)
{
    __shared__ float sW[HID * HID];    // 16 KB
    __shared__ float sF[16][HID];      // 4 KB
    int tid = threadIdx.x;
    for (int i = tid; i < HID * HID; i += 256) sW[i] = W2[i];
    int row0 = blockIdx.x * 16;
    for (int i = tid; i < 16 * HID; i += 256)
        sF[i >> 6][i & 63] = h[row0 * HID + i];
    __syncthreads();
    int rg = tid >> 6, j = tid & 63;
    float acc0 = b2[j], acc1 = acc0, acc2 = acc0, acc3 = acc0;
#pragma unroll
    for (int k = 0; k < HID; k++) {
        float w = sW[k * HID + j];
        acc0 = fmaf(sF[rg     ][k], w, acc0);
        acc1 = fmaf(sF[rg +  4][k], w, acc1);
        acc2 = fmaf(sF[rg +  8][k], w, acc2);
        acc3 = fmaf(sF[rg + 12][k], w, acc3);
    }
    out[(row0 + rg     ) * HID + j] = acc0;
    out[(row0 + rg +  4) * HID + j] = acc1;
    out[(row0 + rg +  8) * HID + j] = acc2;
    out[(row0 + rg + 12) * HID + j] = acc3;
}

// ---------------------------------------------------------------------------
extern "C" void kernel_launch(void* const* d_in, const int* in_sizes, int n_in,
                              void* d_out, int out_size)
{
    const float* feat  = (const float*)d_in[0];
    const int*   src   = (const int*)  d_in[1];
    const int*   dst   = (const int*)  d_in[2];
    const float* W1    = (const float*)d_in[3];
    const float* b1    = (const float*)d_in[4];
    const float* W2    = (const float*)d_in[5];
    const float* b2    = (const float*)d_in[6];
    const float* betas = (const float*)d_in[7];

    float *h0, *h1, *rnA, *rnB; int *deg, *off, *cur, *bsum, *csr;
    cudaGetSymbolAddress((void**)&h0,   g_h0);
    cudaGetSymbolAddress((void**)&h1,   g_h1);
    cudaGetSymbolAddress((void**)&rnA,  g_rnA);
    cudaGetSymbolAddress((void**)&rnB,  g_rnB);
    cudaGetSymbolAddress((void**)&deg,  g_deg);
    cudaGetSymbolAddress((void**)&off,  g_off);
    cudaGetSymbolAddress((void**)&cur,  g_cur);
    cudaGetSymbolAddress((void**)&bsum, g_bsum);
    cudaGetSymbolAddress((void**)&csr,  g_csr);

    // CSR by destination (built once per launch, reused by both layers)
    zero_deg_kernel<<<N_NODES / 256, 256>>>(deg);
    hist_kernel<<<N_EDGES / 256, 256>>>(dst, deg);
    scan1_kernel<<<N_NODES / 256, 256>>>(deg, off, bsum);
    scan23_kernel<<<N_NODES / 256, 256>>>(off, bsum, cur);
    scatter_kernel<<<N_EDGES / 256, 256>>>(src, dst, cur, csr);

    proj_kernel<<<N_NODES / 16, 256>>>(feat, W1, b1, h0, rnA);

    layer_kernel<<<N_NODES * 32 / 256, 256>>>(csr, off, h0, rnA, betas, 0, h1, rnB);
    layer_kernel<<<N_NODES * 32 / 256, 256>>>(csr, off, h1, rnB, betas, 1, h0, rnA);

    cls_kernel<<<N_NODES / 16, 256>>>(h0, W2, b2, (float*)d_out);
}

// round 6
// speedup vs baseline: 4.4203x; 1.0483x over previous
#include <cuda_runtime.h>
#include <math_constants.h>

#define N_NODES 65536
#define N_EDGES 1048576
#define IN_F 128
#define HID 64

// ---------------- scratch (device globals; no allocation allowed) ----------
__device__ float g_h0[N_NODES * HID];   // 16 MB
__device__ float g_h1[N_NODES * HID];   // 16 MB
__device__ float g_rnA[N_NODES];        // 1/max(||h||, eps) ping
__device__ float g_rnB[N_NODES];        // pong
__device__ int   g_deg[N_NODES];
__device__ int   g_off[N_NODES + 1];
__device__ int   g_cur[N_NODES];
__device__ int   g_bsum[256];
__device__ int   g_csr[N_EDGES];        // src node id, grouped by dst

// ---------------- CSR build --------------------------------------------------
__global__ __launch_bounds__(256) void zero_deg_kernel(int* __restrict__ deg) {
    deg[blockIdx.x * 256 + threadIdx.x] = 0;
}

__global__ __launch_bounds__(256) void hist_kernel(
    const int* __restrict__ dst, int* __restrict__ deg) {
    int i = blockIdx.x * 256 + threadIdx.x;
    atomicAdd(deg + __ldg(dst + i), 1);
}

__global__ __launch_bounds__(256) void scan1_kernel(
    const int* __restrict__ deg, int* __restrict__ off, int* __restrict__ bsum) {
    __shared__ int s[256];
    int t = threadIdx.x;
    int g = blockIdx.x * 256 + t;
    int d = deg[g];
    s[t] = d;
    __syncthreads();
#pragma unroll
    for (int o = 1; o < 256; o <<= 1) {
        int v = (t >= o) ? s[t - o] : 0;
        __syncthreads();
        s[t] += v;
        __syncthreads();
    }
    off[g] = s[t] - d;
    if (t == 255) bsum[blockIdx.x] = s[255];
}

// every block redundantly scans the 256 block sums, then applies offsets
__global__ __launch_bounds__(256) void scan23_kernel(
    int* __restrict__ off, const int* __restrict__ bsum, int* __restrict__ cur) {
    __shared__ int s[256];
    int t = threadIdx.x;
    int d = bsum[t];
    s[t] = d;
    __syncthreads();
#pragma unroll
    for (int o = 1; o < 256; o <<= 1) {
        int v = (t >= o) ? s[t - o] : 0;
        __syncthreads();
        s[t] += v;
        __syncthreads();
    }
    __syncthreads();
    int i = blockIdx.x * 256 + t;
    int b = i >> 8;
    int excl = s[b] - bsum[b];
    int v = off[i] + excl;
    off[i] = v;
    cur[i] = v;
    if (i == 0) off[N_NODES] = N_EDGES;
}

__global__ __launch_bounds__(256) void scatter_kernel(
    const int* __restrict__ src, const int* __restrict__ dst,
    int* __restrict__ cur, int* __restrict__ csr) {
    int i = blockIdx.x * 256 + threadIdx.x;
    int p = atomicAdd(cur + __ldg(dst + i), 1);
    csr[p] = __ldg(src + i);
}

// ---------------- proj: h = relu(features @ W1 + b1) + fused row norms ------
__global__ __launch_bounds__(256) void proj_kernel(
    const float* __restrict__ feat, const float* __restrict__ W1,
    const float* __restrict__ b1, float* __restrict__ out,
    float* __restrict__ rn)
{
    __shared__ float sW[IN_F * HID];   // 32 KB
    __shared__ float sF[16][IN_F];     // 8 KB
    __shared__ float sN[16];
    int tid = threadIdx.x;
    if (tid < 16) sN[tid] = 0.0f;
    for (int i = tid; i < IN_F * HID; i += 256) sW[i] = W1[i];
    int row0 = blockIdx.x * 16;
    for (int i = tid; i < 16 * IN_F; i += 256)
        sF[i >> 7][i & 127] = feat[row0 * IN_F + i];
    __syncthreads();
    int rg = tid >> 6, j = tid & 63;
    float acc0 = b1[j], acc1 = acc0, acc2 = acc0, acc3 = acc0;
#pragma unroll
    for (int k = 0; k < IN_F; k++) {
        float w = sW[k * HID + j];
        acc0 = fmaf(sF[rg     ][k], w, acc0);
        acc1 = fmaf(sF[rg +  4][k], w, acc1);
        acc2 = fmaf(sF[rg +  8][k], w, acc2);
        acc3 = fmaf(sF[rg + 12][k], w, acc3);
    }
    acc0 = fmaxf(acc0, 0.0f); acc1 = fmaxf(acc1, 0.0f);
    acc2 = fmaxf(acc2, 0.0f); acc3 = fmaxf(acc3, 0.0f);
    out[(row0 + rg     ) * HID + j] = acc0;
    out[(row0 + rg +  4) * HID + j] = acc1;
    out[(row0 + rg +  8) * HID + j] = acc2;
    out[(row0 + rg + 12) * HID + j] = acc3;
    float p0 = acc0 * acc0, p1 = acc1 * acc1;
    float p2 = acc2 * acc2, p3 = acc3 * acc3;
#pragma unroll
    for (int o = 16; o; o >>= 1) {
        p0 += __shfl_xor_sync(0xffffffffu, p0, o);
        p1 += __shfl_xor_sync(0xffffffffu, p1, o);
        p2 += __shfl_xor_sync(0xffffffffu, p2, o);
        p3 += __shfl_xor_sync(0xffffffffu, p3, o);
    }
    if ((tid & 31) == 0) {
        atomicAdd(&sN[rg     ], p0);
        atomicAdd(&sN[rg +  4], p1);
        atomicAdd(&sN[rg +  8], p2);
        atomicAdd(&sN[rg + 12], p3);
    }
    __syncthreads();
    if (tid < 16)
        rn[row0 + tid] = 1.0f / fmaxf(sqrtf(sN[tid]), 1e-12f);
}

// ---------------- fused AGNN layer: warp/dst, 2 edges per step --------------
// lane = 16*half + sub; lane owns float4 elems [sub*4, sub*4+4) of the 64-dim
// vectors; half-warp `half` owns edge (j + half) of each pair.
__global__ __launch_bounds__(256) void layer_kernel(
    const int* __restrict__ csr, const int* __restrict__ off,
    const float* __restrict__ h, const float* __restrict__ rn_in,
    const float* __restrict__ betas, int layer,
    float* __restrict__ out, float* __restrict__ rn_out)
{
    int node = (blockIdx.x * blockDim.x + threadIdx.x) >> 5;
    int lane = threadIdx.x & 31;
    int sub  = lane & 15;
    int half = lane >> 4;
    const unsigned FULL = 0xffffffffu;

    int s0 = off[node], s1 = off[node + 1];
    float beta = __ldg(betas + layer);
    float B = fabsf(beta);                         // analytic max of beta*cos
    float4 q = *(const float4*)(h + node * HID + sub * 4);
    float qs = beta * rn_in[node];
    q.x *= qs; q.y *= qs; q.z *= qs; q.w *= qs;

    float ss = 0.0f;
    float4 acc = make_float4(0.f, 0.f, 0.f, 0.f);

    for (int base = s0; base < s1; base += 32) {
        int inb = (base + lane < s1);
        int idx = inb ? __ldg(csr + base + lane) : 0;
        float rnl = inb ? rn_in[idx] : 0.0f;
        int cnt = min(32, s1 - base);
        for (int j = 0; j < cnt; j += 4) {
            int pe0 = j + half;                    // pair 0 edge slot
            int pe1 = j + 2 + half;                // pair 1 edge slot
            int   sn0 = __shfl_sync(FULL, idx, pe0);
            int   sn1 = __shfl_sync(FULL, idx, pe1 & 31);
            float rs0 = __shfl_sync(FULL, rnl, pe0);
            float rs1 = __shfl_sync(FULL, rnl, pe1 & 31);
            bool v0 = (base + pe0 < s1);
            bool v1 = (pe1 < cnt) && (base + pe1 < s1);
            float4 a0 = *(const float4*)(h + sn0 * HID + sub * 4);
            float4 a1 = *(const float4*)(h + sn1 * HID + sub * 4);
            float d0 = q.x*a0.x + q.y*a0.y + q.z*a0.z + q.w*a0.w;
            float d1 = q.x*a1.x + q.y*a1.y + q.z*a1.z + q.w*a1.w;
#pragma unroll
            for (int o = 1; o <= 8; o <<= 1) {
                d0 += __shfl_xor_sync(FULL, d0, o);
                d1 += __shfl_xor_sync(FULL, d1, o);
            }
            float w0 = __expf(fmaf(d0, rs0, -B));
            float w1 = __expf(fmaf(d1, rs1, -B));
            w0 = v0 ? w0 : 0.0f;
            w1 = v1 ? w1 : 0.0f;
            ss += w0 + w1;
            acc.x = fmaf(w0, a0.x, acc.x); acc.x = fmaf(w1, a1.x, acc.x);
            acc.y = fmaf(w0, a0.y, acc.y); acc.y = fmaf(w1, a1.y, acc.y);
            acc.z = fmaf(w0, a0.z, acc.z); acc.z = fmaf(w1, a1.z, acc.z);
            acc.w = fmaf(w0, a0.w, acc.w); acc.w = fmaf(w1, a1.w, acc.w);
        }
    }
    // combine the two half-warps (each lane's ss is its half's exact edge sum)
    acc.x += __shfl_xor_sync(FULL, acc.x, 16);
    acc.y += __shfl_xor_sync(FULL, acc.y, 16);
    acc.z += __shfl_xor_sync(FULL, acc.z, 16);
    acc.w += __shfl_xor_sync(FULL, acc.w, 16);
    ss    += __shfl_xor_sync(FULL, ss, 16);
    float inv = (s1 > s0) ? __frcp_rn(ss) : 0.0f;
    float4 o4 = make_float4(acc.x * inv, acc.y * inv, acc.z * inv, acc.w * inv);
    float ns = o4.x*o4.x + o4.y*o4.y + o4.z*o4.z + o4.w*o4.w;
#pragma unroll
    for (int o = 1; o <= 8; o <<= 1)
        ns += __shfl_xor_sync(FULL, ns, o);
    if (half == 0) {
        *(float4*)(out + node * HID + sub * 4) = o4;
        if (sub == 0)
            rn_out[node] = 1.0f / fmaxf(sqrtf(ns), 1e-12f);
    }
}

// ---------------- cls: out = h @ W2 + b2, 16 rows/block ---------------------
__global__ __launch_bounds__(256) void cls_kernel(
    const float* __restrict__ h, const float* __restrict__ W2,
    const float* __restrict__ b2, float* __restrict__ out)
{
    __shared__ float sW[HID * HID];    // 16 KB
    __shared__ float sF[16][HID];      // 4 KB
    int tid = threadIdx.x;
    for (int i = tid; i < HID * HID; i += 256) sW[i] = W2[i];
    int row0 = blockIdx.x * 16;
    for (int i = tid; i < 16 * HID; i += 256)
        sF[i >> 6][i & 63] = h[row0 * HID + i];
    __syncthreads();
    int rg = tid >> 6, j = tid & 63;
    float acc0 = b2[j], acc1 = acc0, acc2 = acc0, acc3 = acc0;
#pragma unroll
    for (int k = 0; k < HID; k++) {
        float w = sW[k * HID + j];
        acc0 = fmaf(sF[rg     ][k], w, acc0);
        acc1 = fmaf(sF[rg +  4][k], w, acc1);
        acc2 = fmaf(sF[rg +  8][k], w, acc2);
        acc3 = fmaf(sF[rg + 12][k], w, acc3);
    }
    out[(row0 + rg     ) * HID + j] = acc0;
    out[(row0 + rg +  4) * HID + j] = acc1;
    out[(row0 + rg +  8) * HID + j] = acc2;
    out[(row0 + rg + 12) * HID + j] = acc3;
}

// ---------------------------------------------------------------------------
extern "C" void kernel_launch(void* const* d_in, const int* in_sizes, int n_in,
                              void* d_out, int out_size)
{
    const float* feat  = (const float*)d_in[0];
    const int*   src   = (const int*)  d_in[1];
    const int*   dst   = (const int*)  d_in[2];
    const float* W1    = (const float*)d_in[3];
    const float* b1    = (const float*)d_in[4];
    const float* W2    = (const float*)d_in[5];
    const float* b2    = (const float*)d_in[6];
    const float* betas = (const float*)d_in[7];

    float *h0, *h1, *rnA, *rnB; int *deg, *off, *cur, *bsum, *csr;
    cudaGetSymbolAddress((void**)&h0,   g_h0);
    cudaGetSymbolAddress((void**)&h1,   g_h1);
    cudaGetSymbolAddress((void**)&rnA,  g_rnA);
    cudaGetSymbolAddress((void**)&rnB,  g_rnB);
    cudaGetSymbolAddress((void**)&deg,  g_deg);
    cudaGetSymbolAddress((void**)&off,  g_off);
    cudaGetSymbolAddress((void**)&cur,  g_cur);
    cudaGetSymbolAddress((void**)&bsum, g_bsum);
    cudaGetSymbolAddress((void**)&csr,  g_csr);

    // CSR by destination (built once, reused by both layers)
    zero_deg_kernel<<<N_NODES / 256, 256>>>(deg);
    hist_kernel<<<N_EDGES / 256, 256>>>(dst, deg);
    scan1_kernel<<<N_NODES / 256, 256>>>(deg, off, bsum);
    scan23_kernel<<<N_NODES / 256, 256>>>(off, bsum, cur);
    scatter_kernel<<<N_EDGES / 256, 256>>>(src, dst, cur, csr);

    proj_kernel<<<N_NODES / 16, 256>>>(feat, W1, b1, h0, rnA);

    layer_kernel<<<N_NODES * 32 / 256, 256>>>(csr, off, h0, rnA, betas, 0, h1, rnB);
    layer_kernel<<<N_NODES * 32 / 256, 256>>>(csr, off, h1, rnB, betas, 1, h0, rnA);

    cls_kernel<<<N_NODES / 16, 256>>>(h0, W2, b2, (float*)d_out);
}